// round 11
// baseline (speedup 1.0000x reference)
#include <cuda_runtime.h>

#define N_NODES 100000
#define N_EDGES 800000
#define NF 64
#define NH 16
#define NG 64

// ---------------- device scratch (no allocations allowed) ----------------
__device__ __align__(16) float g_y1[N_NODES * NH];      // x @ W1_rel
__device__ __align__(16) float g_root1[N_NODES * NH];   // x @ W1_root + b1
__device__ __align__(16) float g_agg1[N_NODES * NH];    // edge-aggregated y1
__device__ __align__(16) float g_t[N_NODES];            // h1 . w2r
__device__ float    g_gsum[NG];                          // per-graph running sum
__device__ int      g_gcnt[NG];                          // per-graph node count
__device__ float    g_w2r[NH];
__device__ float    g_w2o[NH];
__device__ float    g_c;
__device__ int      g_is64;
__device__ unsigned g_ticket;

__device__ __forceinline__ int idx_at(const void* p, long long pos, int is64) {
    if (is64) return (int)((const long long*)p)[pos];
    return ((const int*)p)[pos];
}

// ---------------- init: zero scratch + dtype detect + layer-2 fold ----------------
__global__ void k_init(const unsigned int* __restrict__ eiw,
                       const float* __restrict__ W2_rel,
                       const float* __restrict__ W2_root,
                       const float* __restrict__ b2,
                       const float* __restrict__ Wlin) {
    int i = blockIdx.x * blockDim.x + threadIdx.x;
    if (i < N_NODES * NH / 4)
        reinterpret_cast<float4*>(g_agg1)[i] = make_float4(0.f, 0.f, 0.f, 0.f);
    if (i < NG) { g_gsum[i] = 0.f; g_gcnt[i] = 0; }
    if (i == 0) g_ticket = 0u;

    if (blockIdx.x == 0) {
        // dtype detection: node ids < 2^31, so int64 data has all-zero high words.
        __shared__ int any;
        if (threadIdx.x == 0) any = 0;
        __syncthreads();
        int nz = 0;
        #pragma unroll
        for (int q = 0; q < 4; q++)
            if (eiw[(threadIdx.x * 4 + q) * 2 + 1] != 0u) nz = 1;
        if (nz) atomicOr(&any, 1);
        __syncthreads();
        if (threadIdx.x == 0) g_is64 = any ? 0 : 1;
    } else if (blockIdx.x == 1) {
        // fold layer-2 weights through final linear
        int h = threadIdx.x;
        if (h < NH) {
            float a = 0.f, b = 0.f;
            #pragma unroll
            for (int j = 0; j < NH; j++) {
                float wl = Wlin[j];
                a += W2_rel [h * NH + j] * wl;
                b += W2_root[h * NH + j] * wl;
            }
            g_w2r[h] = a;
            g_w2o[h] = b;
        }
        if (h == 0) {
            float c = 0.f;
            #pragma unroll
            for (int j = 0; j < NH; j++) c += b2[j] * Wlin[j];
            g_c = c;
        }
    }
}

// ---------------- node GEMM: 2 nodes per thread (weights LDS amortized) ----------------
__global__ __launch_bounds__(256) void k_node1(
    const float* __restrict__ x,
    const float* __restrict__ W1_rel,
    const float* __restrict__ W1_root,
    const float* __restrict__ b1) {

    __shared__ float sWr[NF * NH];
    __shared__ float sWo[NF * NH];
    __shared__ float sb[NH];
    for (int i = threadIdx.x; i < NF * NH; i += 256) {
        sWr[i] = W1_rel[i];
        sWo[i] = W1_root[i];
    }
    if (threadIdx.x < NH) sb[threadIdx.x] = b1[threadIdx.x];
    __syncthreads();

    int n0 = blockIdx.x * 512 + threadIdx.x;
    int n1 = n0 + 256;
    bool v0 = n0 < N_NODES, v1 = n1 < N_NODES;
    int m0 = v0 ? n0 : 0, m1 = v1 ? n1 : 0;

    float aR0[NH], aO0[NH], aR1[NH], aO1[NH];
    #pragma unroll
    for (int h = 0; h < NH; h++) { aR0[h]=0.f; aO0[h]=0.f; aR1[h]=0.f; aO1[h]=0.f; }

    const float4* x0 = reinterpret_cast<const float4*>(x + (size_t)m0 * NF);
    const float4* x1 = reinterpret_cast<const float4*>(x + (size_t)m1 * NF);

    #pragma unroll 2
    for (int kk = 0; kk < NF / 4; kk++) {
        float4 a4 = x0[kk];
        float4 b4 = x1[kk];
        float as[4] = {a4.x, a4.y, a4.z, a4.w};
        float bs[4] = {b4.x, b4.y, b4.z, b4.w};
        #pragma unroll
        for (int c = 0; c < 4; c++) {
            int k = kk * 4 + c;
            const float* wr = &sWr[k * NH];
            const float* wo = &sWo[k * NH];
            float va = as[c], vb = bs[c];
            #pragma unroll
            for (int h = 0; h < NH; h++) {
                float w1 = wr[h], w2 = wo[h];
                aR0[h] += va * w1;
                aO0[h] += va * w2;
                aR1[h] += vb * w1;
                aO1[h] += vb * w2;
            }
        }
    }

    if (v0) {
        float4* yp = reinterpret_cast<float4*>(g_y1    + (size_t)n0 * NH);
        float4* rp = reinterpret_cast<float4*>(g_root1 + (size_t)n0 * NH);
        #pragma unroll
        for (int q = 0; q < 4; q++) {
            float4 a, b;
            a.x = aR0[q*4+0]; a.y = aR0[q*4+1]; a.z = aR0[q*4+2]; a.w = aR0[q*4+3];
            b.x = aO0[q*4+0] + sb[q*4+0];
            b.y = aO0[q*4+1] + sb[q*4+1];
            b.z = aO0[q*4+2] + sb[q*4+2];
            b.w = aO0[q*4+3] + sb[q*4+3];
            yp[q] = a; rp[q] = b;
        }
    }
    if (v1) {
        float4* yp = reinterpret_cast<float4*>(g_y1    + (size_t)n1 * NH);
        float4* rp = reinterpret_cast<float4*>(g_root1 + (size_t)n1 * NH);
        #pragma unroll
        for (int q = 0; q < 4; q++) {
            float4 a, b;
            a.x = aR1[q*4+0]; a.y = aR1[q*4+1]; a.z = aR1[q*4+2]; a.w = aR1[q*4+3];
            b.x = aO1[q*4+0] + sb[q*4+0];
            b.y = aO1[q*4+1] + sb[q*4+1];
            b.z = aO1[q*4+2] + sb[q*4+2];
            b.w = aO1[q*4+3] + sb[q*4+3];
            yp[q] = a; rp[q] = b;
        }
    }
}

__device__ __forceinline__ void red_add_v4(float* p, float4 v) {
    asm volatile("red.global.add.v4.f32 [%0], {%1,%2,%3,%4};"
                 :: "l"(p), "f"(v.x), "f"(v.y), "f"(v.z), "f"(v.w)
                 : "memory");
}

// Edge pass 1: agg1[dst] += y1[src]; 4 edges/thread, loads front-batched.
#define E1_PER (4 * 256)
__global__ __launch_bounds__(256) void k_edge1(const void* __restrict__ ei) {
    int base = blockIdx.x * E1_PER + threadIdx.x;
    int is64 = g_is64;

    int e[4], s[4], d[4];
    bool p[4];
    #pragma unroll
    for (int q = 0; q < 4; q++) {
        e[q] = base + q * 256;
        p[q] = e[q] < N_EDGES;
        int f = p[q] ? e[q] : 0;
        s[q] = idx_at(ei, f, is64);
        d[q] = idx_at(ei, (long long)N_EDGES + f, is64);
    }

    float4 v[4][4];
    #pragma unroll
    for (int q = 0; q < 4; q++) {
        const float4* y = reinterpret_cast<const float4*>(g_y1 + (size_t)s[q] * NH);
        v[q][0] = y[0]; v[q][1] = y[1]; v[q][2] = y[2]; v[q][3] = y[3];
    }

    #pragma unroll
    for (int q = 0; q < 4; q++) {
        if (p[q]) {
            float* a = g_agg1 + (size_t)d[q] * NH;
            red_add_v4(a,      v[q][0]);
            red_add_v4(a + 4,  v[q][1]);
            red_add_v4(a + 8,  v[q][2]);
            red_add_v4(a + 12, v[q][3]);
        }
    }
}

// Per-node: h1 = relu(agg1+root1); t = h1.w2r -> g_t;
// pool rpart = h1.w2o + c into per-graph bins (fused former k_pool).
__global__ __launch_bounds__(256) void k_node2(const void* __restrict__ batch) {
    __shared__ float swr[NH], swo[NH];
    __shared__ float sc;
    __shared__ float gs[NG];
    __shared__ int   gc[NG];
    if (threadIdx.x < NH) { swr[threadIdx.x] = g_w2r[threadIdx.x]; swo[threadIdx.x] = g_w2o[threadIdx.x]; }
    if (threadIdx.x == 0) sc = g_c;
    if (threadIdx.x < NG) { gs[threadIdx.x] = 0.f; gc[threadIdx.x] = 0; }
    __syncthreads();

    int is64 = g_is64;
    int n0 = blockIdx.x * 512 + threadIdx.x;
    int n1 = n0 + 256;
    bool v0 = n0 < N_NODES, v1 = n1 < N_NODES;
    int m0 = v0 ? n0 : 0, m1 = v1 ? n1 : 0;

    const float4* a0 = reinterpret_cast<const float4*>(g_agg1  + (size_t)m0 * NH);
    const float4* r0 = reinterpret_cast<const float4*>(g_root1 + (size_t)m0 * NH);
    const float4* a1 = reinterpret_cast<const float4*>(g_agg1  + (size_t)m1 * NH);
    const float4* r1 = reinterpret_cast<const float4*>(g_root1 + (size_t)m1 * NH);

    float4 A0[4], R0[4], A1[4], R1[4];
    #pragma unroll
    for (int q = 0; q < 4; q++) { A0[q] = a0[q]; R0[q] = r0[q]; A1[q] = a1[q]; R1[q] = r1[q]; }
    int b0 = idx_at(batch, m0, is64);
    int b1 = idx_at(batch, m1, is64);

    float t0 = 0.f, rr0 = 0.f, t1 = 0.f, rr1 = 0.f;
    #pragma unroll
    for (int q = 0; q < 4; q++) {
        float h00 = fmaxf(A0[q].x + R0[q].x, 0.f);
        float h01 = fmaxf(A0[q].y + R0[q].y, 0.f);
        float h02 = fmaxf(A0[q].z + R0[q].z, 0.f);
        float h03 = fmaxf(A0[q].w + R0[q].w, 0.f);
        t0  += h00*swr[q*4+0] + h01*swr[q*4+1] + h02*swr[q*4+2] + h03*swr[q*4+3];
        rr0 += h00*swo[q*4+0] + h01*swo[q*4+1] + h02*swo[q*4+2] + h03*swo[q*4+3];
        float h10 = fmaxf(A1[q].x + R1[q].x, 0.f);
        float h11 = fmaxf(A1[q].y + R1[q].y, 0.f);
        float h12 = fmaxf(A1[q].z + R1[q].z, 0.f);
        float h13 = fmaxf(A1[q].w + R1[q].w, 0.f);
        t1  += h10*swr[q*4+0] + h11*swr[q*4+1] + h12*swr[q*4+2] + h13*swr[q*4+3];
        rr1 += h10*swo[q*4+0] + h11*swo[q*4+1] + h12*swo[q*4+2] + h13*swo[q*4+3];
    }

    if (v0) {
        g_t[n0] = t0;
        atomicAdd(&gs[b0], rr0 + sc);
        atomicAdd(&gc[b0], 1);
    }
    if (v1) {
        g_t[n1] = t1;
        atomicAdd(&gs[b1], rr1 + sc);
        atomicAdd(&gc[b1], 1);
    }
    __syncthreads();
    if (threadIdx.x < NG) {
        if (gc[threadIdx.x] > 0) atomicAdd(&g_gcnt[threadIdx.x], gc[threadIdx.x]);
        if (gs[threadIdx.x] != 0.f) atomicAdd(&g_gsum[threadIdx.x], gs[threadIdx.x]);
    }
}

// Edge pass 2 + pooling + output: gsum[batch[dst]] += t[src] (smem-binned);
// last block writes the final 64 outputs.
#define E2_PER (4 * 256)
__global__ __launch_bounds__(256) void k_edge2(const void* __restrict__ ei,
                                               const void* __restrict__ batch,
                                               float* __restrict__ out,
                                               const float* __restrict__ blin) {
    __shared__ float gs[NG];
    if (threadIdx.x < NG) gs[threadIdx.x] = 0.f;
    __syncthreads();

    int base = blockIdx.x * E2_PER + threadIdx.x;
    int is64 = g_is64;

    int e[4], s[4], d[4];
    bool p[4];
    #pragma unroll
    for (int q = 0; q < 4; q++) {
        e[q] = base + q * 256;
        p[q] = e[q] < N_EDGES;
        int f = p[q] ? e[q] : 0;
        s[q] = idx_at(ei, f, is64);
        d[q] = idx_at(ei, (long long)N_EDGES + f, is64);
    }
    float tv[4];
    int   bb[4];
    #pragma unroll
    for (int q = 0; q < 4; q++) {
        tv[q] = g_t[s[q]];
        bb[q] = idx_at(batch, d[q], is64);
    }
    #pragma unroll
    for (int q = 0; q < 4; q++)
        if (p[q]) atomicAdd(&gs[bb[q]], tv[q]);

    __syncthreads();
    if (threadIdx.x < NG && gs[threadIdx.x] != 0.f)
        atomicAdd(&g_gsum[threadIdx.x], gs[threadIdx.x]);

    // last block writes output
    __threadfence();
    __shared__ bool last;
    if (threadIdx.x == 0) {
        unsigned old = atomicAdd(&g_ticket, 1u);
        last = (old == gridDim.x - 1);
    }
    __syncthreads();
    if (last && threadIdx.x < NG) {
        float cnt = (float)g_gcnt[threadIdx.x];
        out[threadIdx.x] = g_gsum[threadIdx.x] / fmaxf(cnt, 1.f) + blin[0];
    }
}

// ---------------- launch ----------------
extern "C" void kernel_launch(void* const* d_in, const int* in_sizes, int n_in,
                              void* d_out, int out_size) {
    const float* x       = (const float*)d_in[0];
    const void*  ei      = d_in[1];
    const void*  batch   = d_in[2];
    const float* W1_rel  = (const float*)d_in[3];
    const float* W1_root = (const float*)d_in[4];
    const float* b1      = (const float*)d_in[5];
    const float* W2_rel  = (const float*)d_in[6];
    const float* W2_root = (const float*)d_in[7];
    const float* b2      = (const float*)d_in[8];
    const float* Wlin    = (const float*)d_in[9];
    const float* blin    = (const float*)d_in[10];
    float*       out     = (float*)d_out;

    (void)in_sizes; (void)n_in; (void)out_size;

    k_init <<<(N_NODES * NH / 4 + 255) / 256, 256>>>((const unsigned int*)ei,
                                                     W2_rel, W2_root, b2, Wlin);
    k_node1<<<(N_NODES + 511) / 512, 256>>>(x, W1_rel, W1_root, b1);
    k_edge1<<<(N_EDGES + E1_PER - 1) / E1_PER, 256>>>(ei);
    k_node2<<<(N_NODES + 511) / 512, 256>>>(batch);
    k_edge2<<<(N_EDGES + E2_PER - 1) / E2_PER, 256>>>(ei, batch, out, blin);
}